// round 13
// baseline (speedup 1.0000x reference)
#include <cuda_runtime.h>
#include <cuda_bf16.h>
#include <math.h>
#include <stdint.h>

// ============================================================================
// Problem constants (fixed by reference setup_inputs)
// ============================================================================
#define NTEST  8192
#define NTRAIN 8192
#define DIM    256

#define TM 128
#define TN 128
#define N_ROW_TILES (NTEST / TM)               // 64
#define N_COL_TILES (NTRAIN / TN)              // 64
#define TOT_TILES   (N_ROW_TILES * N_COL_TILES) // 4096
#define GRID 148                                // one wave, 1 CTA/SM
#define THREADS 512

// Scratch (__device__ globals: allocation-free rule)
__device__ float g_XX[NTEST];
__device__ float g_YY[NTRAIN];
__device__ __align__(128) __nv_bfloat16 g_At[NTEST  * DIM];
__device__ __align__(128) __nv_bfloat16 g_Bt[NTRAIN * DIM];

// ============================================================================
// helpers
// ============================================================================
__device__ __forceinline__ uint32_t smem_u32(const void* p) {
    uint32_t a;
    asm("{ .reg .u64 t; cvta.to.shared.u64 t, %1; cvt.u32.u64 %0, t; }" : "=r"(a) : "l"(p));
    return a;
}
__device__ __forceinline__ void cp16(uint32_t dst, const void* src) {
    asm volatile("cp.async.cg.shared.global [%0], [%1], 16;" :: "r"(dst), "l"(src));
}
#define CP_COMMIT() asm volatile("cp.async.commit_group;" ::: "memory")

__device__ __forceinline__ void ldsm_x4(uint32_t (&r)[4], uint32_t addr) {
    asm volatile("ldmatrix.sync.aligned.m8n8.x4.shared.b16 {%0,%1,%2,%3}, [%4];"
                 : "=r"(r[0]), "=r"(r[1]), "=r"(r[2]), "=r"(r[3]) : "r"(addr));
}
__device__ __forceinline__ void mma_16816(float (&c)[4], const uint32_t (&a)[4],
                                          uint32_t b0, uint32_t b1) {
    asm volatile(
        "mma.sync.aligned.m16n8k16.row.col.f32.bf16.bf16.f32 "
        "{%0,%1,%2,%3}, {%4,%5,%6,%7}, {%8,%9}, {%0,%1,%2,%3};"
        : "+f"(c[0]), "+f"(c[1]), "+f"(c[2]), "+f"(c[3])
        : "r"(a[0]), "r"(a[1]), "r"(a[2]), "r"(a[3]), "r"(b0), "r"(b1));
}

// ============================================================================
// Kernel 1: norms + bf16 conversion + out[] = mean_const init
// ============================================================================
__global__ void gp_precompute_kernel(const float* __restrict__ Xtest,
                                     const float* __restrict__ Xtrain,
                                     const float* __restrict__ mean_const,
                                     float* __restrict__ out)
{
    const int warp = threadIdx.x >> 5;
    const int lane = threadIdx.x & 31;
    int row = blockIdx.x * 8 + warp;
    if (row >= NTEST + NTRAIN) return;

    const float* X; float* dst; __nv_bfloat16* bdst; bool isTest;
    if (row < NTEST) { X = Xtest;  dst = g_XX; bdst = g_At; isTest = true; }
    else { row -= NTEST; X = Xtrain; dst = g_YY; bdst = g_Bt; isTest = false; }

    const float* p = X + (size_t)row * DIM;
    __nv_bfloat16* bp = bdst + (size_t)row * DIM;
    float s = 0.f;
    #pragma unroll
    for (int d = 0; d < DIM / 32; d++) {
        float v = p[lane + d * 32];
        s = fmaf(v, v, s);
        bp[lane + d * 32] = __float2bfloat16_rn(v);
    }
    #pragma unroll
    for (int o = 16; o > 0; o >>= 1) s += __shfl_xor_sync(0xffffffffu, s, o);
    if (lane == 0) {
        dst[row] = s;
        if (isTest) out[row] = *mean_const;
    }
}

// ============================================================================
// Kernel 2: bf16 HMMA screening GEMM + underflow-exact epilogue.
// 512 threads (4 warps/SMSP), 16 warps in 4x4, warp tile 32x32 (acc=32 regs,
// single-buffered frags) so the whole thing fits the 128-reg/thread cap with
// zero spill. Occupancy — not instruction scheduling — hides LDSM latency.
// ============================================================================
__global__ __launch_bounds__(THREADS, 1)
void gp_hmma_kernel(const float* __restrict__ Xtest,
                    const float* __restrict__ Xtrain,
                    const float* __restrict__ mu,
                    const float* __restrict__ ls_p,
                    const float* __restrict__ sv_p,
                    float* __restrict__ out)
{
    extern __shared__ char dsm[];
    __shared__ float s_yy[2][TN];
    __shared__ float s_mu[2][TN];

    const int tid  = threadIdx.x;
    const int wid  = tid >> 5;
    const int lane = tid & 31;
    const int bid  = blockIdx.x;

    const uint32_t dsm_u = smem_u32(dsm);
    const uint32_t uA  = (dsm_u + 1023u) & ~1023u;
    const uint32_t uB0 = uA  + 65536u;
    const uint32_t uB1 = uB0 + 65536u;

    const int warp_m = (wid & 3) * 32;   // 4 warps along M
    const int warp_n = (wid >> 2) * 32;  // 4 warps along N

    // ldmatrix lane geometry
    const int rA0   = warp_m + (lane & 15);
    const uint32_t swA = (uint32_t)((rA0 & 7) << 4);
    const uint32_t aKl = (uint32_t)((lane >> 4) << 4);
    const int rB0   = warp_n + (lane & 7) + ((lane >> 4) << 3);
    const uint32_t swB = (uint32_t)((rB0 & 7) << 4);
    const uint32_t bKl = (uint32_t)(((lane >> 3) & 1) << 4);

    uint32_t rbaseA[2], rbaseB[2];
    #pragma unroll
    for (int mf = 0; mf < 2; mf++) rbaseA[mf] = uA + (uint32_t)((rA0 + 16 * mf) << 7);
    #pragma unroll
    for (int np = 0; np < 2; np++) rbaseB[np] = (uint32_t)((rB0 + 16 * np) << 7);

    const float l      = *ls_p;
    const float negInv = -0.5f / (l * l);
    const float sCut   = 211.0f * l * l;   // expf == exactly 0 above this
    const float sv     = *sv_p;

    const int t_begin = (int)(((long long)bid     * TOT_TILES) / GRID);
    const int t_end   = (int)(((long long)(bid+1) * TOT_TILES) / GRID);

    // tile fill: 8192 x 16B chunks via cp.async with swizzle (512 threads)
    auto fill_tile = [&](uint32_t ubase, const __nv_bfloat16* src) {
        #pragma unroll
        for (int q0 = 0; q0 < 8; q0++) {
            const int q = q0 * THREADS + tid;
            const int r = q >> 5, c16 = q & 31;
            const uint32_t dst = ubase + (uint32_t)(((c16 >> 3) << 14) + (r << 7)
                                + (((c16 & 7) << 4) ^ ((r & 7) << 4)));
            cp16(dst, src + r * DIM + c16 * 8);
        }
    };

    int i = t_begin;
    while (i < t_end) {
        const int rt      = i >> 6;
        const int seg_end = min(t_end, (rt + 1) << 6);
        const int n       = seg_end - i;
        const int row0    = rt * TM;

        fill_tile(uA, g_At + (size_t)row0 * DIM);
        CP_COMMIT();
        {
            const int n0 = (i & 63) * TN;
            fill_tile(uB0, g_Bt + (size_t)n0 * DIM);
            CP_COMMIT();
            if (tid < TN)                           s_yy[0][tid] = g_YY[n0 + tid];
            else if (tid >= 256 && tid < 256 + TN)  s_mu[0][tid - 256] = mu[n0 + tid - 256];
        }

        // per-thread xx values (4 rows of the 32-row warp stripe) + warp min
        float xv[4];
        #pragma unroll
        for (int j = 0; j < 4; j++) xv[j] = g_XX[row0 + warp_m + (lane >> 2) + 8 * j];
        float xmin = fminf(fminf(xv[0], xv[1]), fminf(xv[2], xv[3]));
        #pragma unroll
        for (int o = 16; o > 0; o >>= 1) xmin = fminf(xmin, __shfl_xor_sync(0xffffffffu, xmin, o));

        for (int tl = 0; tl < n; tl++) {
            const int buf = tl & 1;
            const uint32_t uB = buf ? uB1 : uB0;

            const bool more = (tl + 1 < n);
            if (more) {
                const int n0n = ((i + tl + 1) & 63) * TN;
                fill_tile(buf ? uB0 : uB1, g_Bt + (size_t)n0n * DIM);
                CP_COMMIT();
                if (tid < TN)                           s_yy[buf ^ 1][tid] = g_YY[n0n + tid];
                else if (tid >= 256 && tid < 256 + TN)  s_mu[buf ^ 1][tid - 256] = mu[n0n + tid - 256];
            }
            if (more) asm volatile("cp.async.wait_group 1;" ::: "memory");
            else      asm volatile("cp.async.wait_group 0;" ::: "memory");
            __syncthreads();

            // ---- MMA: 128x128x256 via 32x32 warp tiles, single-buffered frags ----
            float acc[2][4][4];
            #pragma unroll
            for (int mf = 0; mf < 2; mf++)
                #pragma unroll
                for (int nf = 0; nf < 4; nf++)
                    #pragma unroll
                    for (int e = 0; e < 4; e++) acc[mf][nf][e] = 0.f;

            #pragma unroll
            for (int kk = 0; kk < 16; kk++) {
                const uint32_t kcOff = (uint32_t)((kk >> 2) << 14);
                const uint32_t oA = kcOff + ((((uint32_t)(kk & 3) << 5) + aKl) ^ swA);
                const uint32_t oB = kcOff + ((((uint32_t)(kk & 3) << 5) + bKl) ^ swB);

                uint32_t a[2][4], b[2][4];
                ldsm_x4(a[0], rbaseA[0] + oA);
                ldsm_x4(a[1], rbaseA[1] + oA);
                ldsm_x4(b[0], uB + rbaseB[0] + oB);
                ldsm_x4(b[1], uB + rbaseB[1] + oB);

                #pragma unroll
                for (int mf = 0; mf < 2; mf++)
                    #pragma unroll
                    for (int nf = 0; nf < 4; nf++)
                        mma_16816(acc[mf][nf], a[mf],
                                  b[nf >> 1][(nf & 1) * 2], b[nf >> 1][(nf & 1) * 2 + 1]);
            }

            // ---- epilogue: warp-level rigorous screen over 32x32 ----
            float cmax = -3.4e38f;
            #pragma unroll
            for (int mf = 0; mf < 2; mf++)
                #pragma unroll
                for (int nf = 0; nf < 4; nf++)
                    #pragma unroll
                    for (int e = 0; e < 4; e++) cmax = fmaxf(cmax, acc[mf][nf][e]);
            #pragma unroll
            for (int o = 16; o > 0; o >>= 1) cmax = fmaxf(cmax, __shfl_xor_sync(0xffffffffu, cmax, o));

            float ymin = s_yy[buf][warp_n + lane];
            #pragma unroll
            for (int o = 16; o > 0; o >>= 1) ymin = fminf(ymin, __shfl_xor_sync(0xffffffffu, ymin, o));

            const float qmin  = xmin + ymin;                       // q = xx+yy >= 0
            const float lbmin = fmaf(-0.0078125f, qmin, fmaf(-2.f, cmax, qmin));

            if (lbmin < sCut) {   // rare: per-element check + exact fp32 recompute
                float yv[8];
                #pragma unroll
                for (int k2 = 0; k2 < 8; k2++)
                    yv[k2] = s_yy[buf][warp_n + (k2 >> 1) * 8 + 2 * (lane & 3) + (k2 & 1)];
                const int n0 = ((i + tl) & 63) * TN;
                #pragma unroll 1
                for (int mf = 0; mf < 2; mf++)
                    for (int nf = 0; nf < 4; nf++)
                        for (int e = 0; e < 4; e++) {
                            const float q  = xv[mf * 2 + (e >> 1)] + yv[nf * 2 + (e & 1)];
                            const float s  = fmaf(-2.f, acc[mf][nf][e], q);
                            const float lb = fmaf(-0.0078125f, q, s);
                            if (lb < sCut) {
                                const int rg = row0 + warp_m + mf * 16 + (lane >> 2) + 8 * (e >> 1);
                                const int cg = n0 + warp_n + nf * 8 + 2 * (lane & 3) + (e & 1);
                                const float* xr = Xtest  + (size_t)rg * DIM;
                                const float* yr = Xtrain + (size_t)cg * DIM;
                                float cr = 0.f;
                                #pragma unroll 8
                                for (int d = 0; d < DIM; d++) cr = fmaf(xr[d], yr[d], cr);
                                const float se = fmaxf(fmaf(-2.f, cr, g_XX[rg] + g_YY[cg]), 0.f);
                                const float ev = expf(se * negInv);
                                if (ev != 0.f)
                                    atomicAdd(&out[rg], sv * ev * s_mu[buf][warp_n + nf * 8 + 2 * (lane & 3) + (e & 1)]);
                            }
                        }
            }
            __syncthreads();   // epilogue done before buffers are overwritten
        }
        i = seg_end;
    }
}

// ============================================================================
// kernel_launch: inputs in metadata order:
//   0 Xtest, 1 Xtrain, 2 mu, 3 mean_const, 4 lengthscale, 5 signal_var
// ============================================================================
extern "C" void kernel_launch(void* const* d_in, const int* in_sizes, int n_in,
                              void* d_out, int out_size)
{
    const float* Xtest      = (const float*)d_in[0];
    const float* Xtrain     = (const float*)d_in[1];
    const float* mu         = (const float*)d_in[2];
    const float* mean_const = (const float*)d_in[3];
    const float* lengthsc   = (const float*)d_in[4];
    const float* signal_var = (const float*)d_in[5];
    float* out = (float*)d_out;

    const int DYN = 3 * 65536 + 1024;
    cudaFuncSetAttribute(gp_hmma_kernel, cudaFuncAttributeMaxDynamicSharedMemorySize, DYN);

    gp_precompute_kernel<<<(NTEST + NTRAIN) / 8, 256>>>(Xtest, Xtrain, mean_const, out);
    gp_hmma_kernel<<<GRID, THREADS, DYN>>>(Xtest, Xtrain, mu, lengthsc, signal_var, out);
}

// round 14
// speedup vs baseline: 1.1673x; 1.1673x over previous
#include <cuda_runtime.h>
#include <cuda_fp16.h>
#include <math.h>
#include <stdint.h>

// ============================================================================
// Problem constants (fixed by reference setup_inputs)
// ============================================================================
#define NTEST  8192
#define NTRAIN 8192
#define DIM    256

#define TM 128
#define TN 128
#define N_ROW_TILES (NTEST / TM)               // 64
#define N_COL_TILES (NTRAIN / TN)              // 64
#define TOT_TILES   (N_ROW_TILES * N_COL_TILES) // 4096
#define GRID 296                                // 2 balanced waves on 148 SMs

// Scratch (__device__ globals: allocation-free rule)
__device__ float g_XX[NTEST];
__device__ float g_YY[NTRAIN];
__device__ int   g_sat = 0;   // sticky: norm too large for f16-acc bound -> exact path
__device__ __align__(128) __half g_At[NTEST  * DIM];
__device__ __align__(128) __half g_Bt[NTRAIN * DIM];

// ============================================================================
// helpers
// ============================================================================
__device__ __forceinline__ uint32_t smem_u32(const void* p) {
    uint32_t a;
    asm("{ .reg .u64 t; cvta.to.shared.u64 t, %1; cvt.u32.u64 %0, t; }" : "=r"(a) : "l"(p));
    return a;
}
__device__ __forceinline__ void cp16(uint32_t dst, const void* src) {
    asm volatile("cp.async.cg.shared.global [%0], [%1], 16;" :: "r"(dst), "l"(src));
}
#define CP_COMMIT() asm volatile("cp.async.commit_group;" ::: "memory")

__device__ __forceinline__ void ldsm_x4(uint32_t (&r)[4], uint32_t addr) {
    asm volatile("ldmatrix.sync.aligned.m8n8.x4.shared.b16 {%0,%1,%2,%3}, [%4];"
                 : "=r"(r[0]), "=r"(r[1]), "=r"(r[2]), "=r"(r[3]) : "r"(addr));
}
// f16 x f16 -> f16 accumulate (D/C packed as 2x f16x2):
//   c[0] = (row r   , col c..c+1), c[1] = (row r+8, col c..c+1)
__device__ __forceinline__ void mma_f16acc(uint32_t (&c)[2], const uint32_t (&a)[4],
                                           uint32_t b0, uint32_t b1) {
    asm volatile(
        "mma.sync.aligned.m16n8k16.row.col.f16.f16.f16.f16 "
        "{%0,%1}, {%2,%3,%4,%5}, {%6,%7}, {%0,%1};"
        : "+r"(c[0]), "+r"(c[1])
        : "r"(a[0]), "r"(a[1]), "r"(a[2]), "r"(a[3]), "r"(b0), "r"(b1));
}

// ============================================================================
// Kernel 1: norms + f16 conversion + overflow guard + out[] = mean_const init
// ============================================================================
__global__ void gp_precompute_kernel(const float* __restrict__ Xtest,
                                     const float* __restrict__ Xtrain,
                                     const float* __restrict__ mean_const,
                                     float* __restrict__ out)
{
    const int warp = threadIdx.x >> 5;
    const int lane = threadIdx.x & 31;
    int row = blockIdx.x * 8 + warp;
    if (row >= NTEST + NTRAIN) return;

    const float* X; float* dst; __half* bdst; bool isTest;
    if (row < NTEST) { X = Xtest;  dst = g_XX; bdst = g_At; isTest = true; }
    else { row -= NTEST; X = Xtrain; dst = g_YY; bdst = g_Bt; isTest = false; }

    const float* p = X + (size_t)row * DIM;
    __half* bp = bdst + (size_t)row * DIM;
    float s = 0.f;
    #pragma unroll
    for (int d = 0; d < DIM / 32; d++) {
        float v = p[lane + d * 32];
        s = fmaf(v, v, s);
        bp[lane + d * 32] = __float2half_rn(v);
    }
    #pragma unroll
    for (int o = 16; o > 0; o >>= 1) s += __shfl_xor_sync(0xffffffffu, s, o);
    if (lane == 0) {
        dst[row] = s;
        // |f16 partial sums| <= 0.5005*(xx+yy); guard keeps them < 65504.
        if (!(s <= 30000.f)) atomicOr(&g_sat, 1);
        if (isTest) out[row] = *mean_const;
    }
}

// ============================================================================
// Kernel 2: f16 HMMA (f16 accumulate) screening GEMM, round-5 geometry:
// 256 threads, warps 4x2, warp tile 32x64, fragment double-buffered k-loop,
// A resident + B double-buffered. Screen margin: |ds| <= 0.02*q + 0.05
// (rigorous: f16 input rounding + <=21 f16 roundings of partials <= 0.5005q).
// ============================================================================
__global__ __launch_bounds__(256, 1)
void gp_hmma_kernel(const float* __restrict__ Xtest,
                    const float* __restrict__ Xtrain,
                    const float* __restrict__ mu,
                    const float* __restrict__ ls_p,
                    const float* __restrict__ sv_p,
                    float* __restrict__ out)
{
    extern __shared__ char dsm[];
    __shared__ float s_yy[2][TN];
    __shared__ float s_mu[2][TN];

    const int tid  = threadIdx.x;
    const int wid  = tid >> 5;
    const int lane = tid & 31;
    const int bid  = blockIdx.x;

    const uint32_t dsm_u = smem_u32(dsm);
    const uint32_t uA  = (dsm_u + 1023u) & ~1023u;
    const uint32_t uB0 = uA  + 65536u;
    const uint32_t uB1 = uB0 + 65536u;

    const int warp_m = (wid & 3) * 32;   // 4 warps along M
    const int warp_n = (wid >> 2) * 64;  // 2 warps along N

    // ldmatrix lane geometry
    const int rA0   = warp_m + (lane & 15);
    const uint32_t swA = (uint32_t)((rA0 & 7) << 4);
    const uint32_t aKl = (uint32_t)((lane >> 4) << 4);
    const int rB0   = warp_n + (lane & 7) + ((lane >> 4) << 3);
    const uint32_t swB = (uint32_t)((rB0 & 7) << 4);
    const uint32_t bKl = (uint32_t)(((lane >> 3) & 1) << 4);

    uint32_t rbaseA[2], rbaseB[4];
    #pragma unroll
    for (int mf = 0; mf < 2; mf++) rbaseA[mf] = uA + (uint32_t)((rA0 + 16 * mf) << 7);
    #pragma unroll
    for (int np = 0; np < 4; np++) rbaseB[np] = (uint32_t)((rB0 + 16 * np) << 7);

    const float l      = *ls_p;
    const float negInv = -0.5f / (l * l);
    const float sCut   = 211.0f * l * l;   // expf == exactly 0 above this
    const float sv     = *sv_p;
    const bool  force  = (g_sat != 0);

    const int t_begin = (int)(((long long)bid     * TOT_TILES) / GRID);
    const int t_end   = (int)(((long long)(bid+1) * TOT_TILES) / GRID);

    auto fill_tile = [&](uint32_t ubase, const __half* src) {
        #pragma unroll
        for (int q0 = 0; q0 < 16; q0++) {
            const int q = q0 * 256 + tid;
            const int r = q >> 5, c16 = q & 31;
            const uint32_t dst = ubase + (uint32_t)(((c16 >> 3) << 14) + (r << 7)
                                + (((c16 & 7) << 4) ^ ((r & 7) << 4)));
            cp16(dst, src + r * DIM + c16 * 8);
        }
    };

    int i = t_begin;
    while (i < t_end) {
        const int rt      = i >> 6;
        const int seg_end = min(t_end, (rt + 1) << 6);
        const int n       = seg_end - i;
        const int row0    = rt * TM;

        fill_tile(uA, g_At + (size_t)row0 * DIM);
        CP_COMMIT();
        {
            const int n0 = (i & 63) * TN;
            fill_tile(uB0, g_Bt + (size_t)n0 * DIM);
            CP_COMMIT();
            if (tid < TN) s_yy[0][tid] = g_YY[n0 + tid];
            else          s_mu[0][tid - TN] = mu[n0 + tid - TN];
        }

        // per-thread xx values (4 rows of the 32-row warp stripe) + warp min
        float xv[4];
        #pragma unroll
        for (int j = 0; j < 4; j++) xv[j] = g_XX[row0 + warp_m + (lane >> 2) + 8 * j];
        float xmin = fminf(fminf(xv[0], xv[1]), fminf(xv[2], xv[3]));
        #pragma unroll
        for (int o = 16; o > 0; o >>= 1) xmin = fminf(xmin, __shfl_xor_sync(0xffffffffu, xmin, o));

        for (int tl = 0; tl < n; tl++) {
            const int buf = tl & 1;
            const uint32_t uB = buf ? uB1 : uB0;

            const bool more = (tl + 1 < n);
            if (more) {
                const int n0n = ((i + tl + 1) & 63) * TN;
                fill_tile(buf ? uB0 : uB1, g_Bt + (size_t)n0n * DIM);
                CP_COMMIT();
                if (tid < TN) s_yy[buf ^ 1][tid] = g_YY[n0n + tid];
                else          s_mu[buf ^ 1][tid - TN] = mu[n0n + tid - TN];
            }
            if (more) asm volatile("cp.async.wait_group 1;" ::: "memory");
            else      asm volatile("cp.async.wait_group 0;" ::: "memory");
            __syncthreads();

            // ---- MMA: 128x128x256, f16 accumulate, fragment-double-buffered ----
            uint32_t acc[2][8][2];
            #pragma unroll
            for (int mf = 0; mf < 2; mf++)
                #pragma unroll
                for (int nf = 0; nf < 8; nf++) { acc[mf][nf][0] = 0u; acc[mf][nf][1] = 0u; }

            uint32_t a[2][2][4], b[2][4][4];

            auto ld_frags = [&](int kk, uint32_t (&af)[2][4], uint32_t (&bf)[4][4]) {
                const uint32_t kcOff = (uint32_t)((kk >> 2) << 14);
                const uint32_t oA = kcOff + ((((uint32_t)(kk & 3) << 5) + aKl) ^ swA);
                const uint32_t oB = kcOff + ((((uint32_t)(kk & 3) << 5) + bKl) ^ swB);
                #pragma unroll
                for (int mf = 0; mf < 2; mf++) ldsm_x4(af[mf], rbaseA[mf] + oA);
                #pragma unroll
                for (int np = 0; np < 4; np++) ldsm_x4(bf[np], uB + rbaseB[np] + oB);
            };

            ld_frags(0, a[0], b[0]);
            #pragma unroll
            for (int kk = 0; kk < 16; kk++) {
                const int cur = kk & 1;
                if (kk < 15) ld_frags(kk + 1, a[cur ^ 1], b[cur ^ 1]);
                #pragma unroll
                for (int mf = 0; mf < 2; mf++)
                    #pragma unroll
                    for (int nf = 0; nf < 8; nf++)
                        mma_f16acc(acc[mf][nf], a[cur][mf],
                                   b[cur][nf >> 1][(nf & 1) * 2], b[cur][nf >> 1][(nf & 1) * 2 + 1]);
            }

            // ---- epilogue: warp-level rigorous screen ----
            __half2 m2 = *(const __half2*)&acc[0][0][0];
            #pragma unroll
            for (int mf = 0; mf < 2; mf++)
                #pragma unroll
                for (int nf = 0; nf < 8; nf++) {
                    m2 = __hmax2(m2, *(const __half2*)&acc[mf][nf][0]);
                    m2 = __hmax2(m2, *(const __half2*)&acc[mf][nf][1]);
                }
            float cmax = fmaxf(__low2float(m2), __high2float(m2));
            #pragma unroll
            for (int o = 16; o > 0; o >>= 1) cmax = fmaxf(cmax, __shfl_xor_sync(0xffffffffu, cmax, o));

            float ymin = fminf(s_yy[buf][warp_n + lane], s_yy[buf][warp_n + 32 + lane]);
            #pragma unroll
            for (int o = 16; o > 0; o >>= 1) ymin = fminf(ymin, __shfl_xor_sync(0xffffffffu, ymin, o));

            const float qmin  = xmin + ymin;                       // q = xx+yy >= 0
            const float lbmin = fmaf(-0.02f, qmin, fmaf(-2.f, cmax, qmin)) - 0.05f;

            if (force || lbmin < sCut) {   // per-element screen + exact fp32 recompute
                float yv[16];
                #pragma unroll
                for (int k2 = 0; k2 < 16; k2++)
                    yv[k2] = s_yy[buf][warp_n + (k2 >> 1) * 8 + 2 * (lane & 3) + (k2 & 1)];
                const int n0 = ((i + tl) & 63) * TN;
                #pragma unroll 1
                for (int mf = 0; mf < 2; mf++)
                    for (int nf = 0; nf < 8; nf++)
                        for (int jj = 0; jj < 2; jj++) {
                            const float2 cv = __half22float2(*(const __half2*)&acc[mf][nf][jj]);
                            #pragma unroll
                            for (int p = 0; p < 2; p++) {
                                const float c  = p ? cv.y : cv.x;
                                const float q  = xv[mf * 2 + jj] + yv[nf * 2 + p];
                                const float s  = fmaf(-2.f, c, q);
                                const float lb = fmaf(-0.02f, q, s) - 0.05f;
                                if (force || lb < sCut) {
                                    const int rg = row0 + warp_m + mf * 16 + (lane >> 2) + 8 * jj;
                                    const int cg = n0 + warp_n + nf * 8 + 2 * (lane & 3) + p;
                                    const float* xr = Xtest  + (size_t)rg * DIM;
                                    const float* yr = Xtrain + (size_t)cg * DIM;
                                    float cr = 0.f;
                                    #pragma unroll 8
                                    for (int d = 0; d < DIM; d++) cr = fmaf(xr[d], yr[d], cr);
                                    const float se = fmaxf(fmaf(-2.f, cr, g_XX[rg] + g_YY[cg]), 0.f);
                                    const float ev = expf(se * negInv);
                                    if (ev != 0.f)
                                        atomicAdd(&out[rg], sv * ev * s_mu[buf][warp_n + nf * 8 + 2 * (lane & 3) + p]);
                                }
                            }
                        }
            }
            __syncthreads();   // epilogue done before buffers are overwritten
        }
        i = seg_end;
    }
}

// ============================================================================
// kernel_launch: inputs in metadata order:
//   0 Xtest, 1 Xtrain, 2 mu, 3 mean_const, 4 lengthscale, 5 signal_var
// ============================================================================
extern "C" void kernel_launch(void* const* d_in, const int* in_sizes, int n_in,
                              void* d_out, int out_size)
{
    const float* Xtest      = (const float*)d_in[0];
    const float* Xtrain     = (const float*)d_in[1];
    const float* mu         = (const float*)d_in[2];
    const float* mean_const = (const float*)d_in[3];
    const float* lengthsc   = (const float*)d_in[4];
    const float* signal_var = (const float*)d_in[5];
    float* out = (float*)d_out;

    const int DYN = 3 * 65536 + 1024;
    cudaFuncSetAttribute(gp_hmma_kernel, cudaFuncAttributeMaxDynamicSharedMemorySize, DYN);

    gp_precompute_kernel<<<(NTEST + NTRAIN) / 8, 256>>>(Xtest, Xtrain, mean_const, out);
    gp_hmma_kernel<<<GRID, 256, DYN>>>(Xtest, Xtrain, mu, lengthsc, signal_var, out);
}

// round 15
// speedup vs baseline: 1.2012x; 1.0290x over previous
#include <cuda_runtime.h>
#include <cuda_fp16.h>
#include <math.h>
#include <stdint.h>

// ============================================================================
// Problem constants (fixed by reference setup_inputs)
// ============================================================================
#define NTEST  8192
#define NTRAIN 8192
#define DIM    256

#define TM 128
#define TN 128
#define N_ROW_TILES (NTEST / TM)               // 64
#define N_COL_TILES (NTRAIN / TN)              // 64
#define TOT_TILES   (N_ROW_TILES * N_COL_TILES) // 4096
#define GRID 296                                // 2 balanced waves on 148 SMs
#define TILE_BYTES 65536                        // 128 rows x 256 cols x 2B

// Scratch (__device__ globals: allocation-free rule)
// g_At/g_Bt hold the data PRE-SWIZZLED in tile-major smem image layout:
// tile t = contiguous 64KB block; within it, byte (lr, c16) lives at
// ((c16>>3)<<14) + (lr<<7) + (((c16&7)<<4) ^ ((lr&7)<<4)).
__device__ float g_XX[NTEST];
__device__ float g_YY[NTRAIN];
__device__ int   g_sat = 0;   // sticky: norm too large for f16-acc bound -> exact path
__device__ __align__(128) __half g_At[NTEST  * DIM];
__device__ __align__(128) __half g_Bt[NTRAIN * DIM];

// ============================================================================
// helpers
// ============================================================================
__device__ __forceinline__ uint32_t smem_u32(const void* p) {
    uint32_t a;
    asm("{ .reg .u64 t; cvta.to.shared.u64 t, %1; cvt.u32.u64 %0, t; }" : "=r"(a) : "l"(p));
    return a;
}
__device__ __forceinline__ void cp16(uint32_t dst, const void* src) {
    asm volatile("cp.async.cg.shared.global [%0], [%1], 16;" :: "r"(dst), "l"(src));
}
#define CP_COMMIT() asm volatile("cp.async.commit_group;" ::: "memory")

__device__ __forceinline__ void ldsm_x4(uint32_t (&r)[4], uint32_t addr) {
    asm volatile("ldmatrix.sync.aligned.m8n8.x4.shared.b16 {%0,%1,%2,%3}, [%4];"
                 : "=r"(r[0]), "=r"(r[1]), "=r"(r[2]), "=r"(r[3]) : "r"(addr));
}
// f16 x f16 -> f16 accumulate (D/C packed as 2x f16x2)
__device__ __forceinline__ void mma_f16acc(uint32_t (&c)[2], const uint32_t (&a)[4],
                                           uint32_t b0, uint32_t b1) {
    asm volatile(
        "mma.sync.aligned.m16n8k16.row.col.f16.f16.f16.f16 "
        "{%0,%1}, {%2,%3,%4,%5}, {%6,%7}, {%0,%1};"
        : "+r"(c[0]), "+r"(c[1])
        : "r"(a[0]), "r"(a[1]), "r"(a[2]), "r"(a[3]), "r"(b0), "r"(b1));
}

// ============================================================================
// Kernel 1: norms + f16 conversion into PRE-SWIZZLED tile-major layout
//           + overflow guard + out[] = mean_const init
// ============================================================================
__global__ void gp_precompute_kernel(const float* __restrict__ Xtest,
                                     const float* __restrict__ Xtrain,
                                     const float* __restrict__ mean_const,
                                     float* __restrict__ out)
{
    const int warp = threadIdx.x >> 5;
    const int lane = threadIdx.x & 31;
    int row = blockIdx.x * 8 + warp;
    if (row >= NTEST + NTRAIN) return;

    const float* X; float* dst; __half* bdst; bool isTest;
    if (row < NTEST) { X = Xtest;  dst = g_XX; bdst = g_At; isTest = true; }
    else { row -= NTEST; X = Xtrain; dst = g_YY; bdst = g_Bt; isTest = false; }

    // lane handles 8 consecutive floats (one 16B output chunk: c16 = lane)
    const float4* p4 = (const float4*)(X + (size_t)row * DIM) + 2 * lane;
    const float4 v0 = p4[0], v1 = p4[1];
    float v[8] = {v0.x, v0.y, v0.z, v0.w, v1.x, v1.y, v1.z, v1.w};

    float s = 0.f;
    __half h[8];
    #pragma unroll
    for (int j = 0; j < 8; j++) {
        s = fmaf(v[j], v[j], s);
        h[j] = __float2half_rn(v[j]);
    }

    // swizzled destination inside this row's tile block
    const int tile = row >> 7, lr = row & 127, c16 = lane;
    const uint32_t off = (uint32_t)(((c16 >> 3) << 14) + (lr << 7)
                        + (((c16 & 7) << 4) ^ ((lr & 7) << 4)));
    *(uint4*)((char*)bdst + (size_t)tile * TILE_BYTES + off) = *(const uint4*)h;

    #pragma unroll
    for (int o = 16; o > 0; o >>= 1) s += __shfl_xor_sync(0xffffffffu, s, o);
    if (lane == 0) {
        dst[row] = s;
        // |f16 partial sums| <= 0.5005*(xx+yy); guard keeps them < 65504.
        if (!(s <= 30000.f)) atomicOr(&g_sat, 1);
        if (isTest) out[row] = *mean_const;
    }
}

// ============================================================================
// Kernel 2: f16 HMMA (f16 accumulate) screening GEMM.
// 256 threads, warps 4x2, warp tile 32x64. Tiles pre-swizzled in gmem ->
// linear coalesced cp.async fills. Fragment pipeline depth 3.
// Screen margin: |ds| <= 0.02*q + 0.05 (rigorous f16 input+accum bound).
// ============================================================================
__global__ __launch_bounds__(256, 1)
void gp_hmma_kernel(const float* __restrict__ Xtest,
                    const float* __restrict__ Xtrain,
                    const float* __restrict__ mu,
                    const float* __restrict__ ls_p,
                    const float* __restrict__ sv_p,
                    float* __restrict__ out)
{
    extern __shared__ char dsm[];
    __shared__ float s_yy[2][TN];
    __shared__ float s_mu[2][TN];

    const int tid  = threadIdx.x;
    const int wid  = tid >> 5;
    const int lane = tid & 31;
    const int bid  = blockIdx.x;

    const uint32_t dsm_u = smem_u32(dsm);
    const uint32_t uA  = (dsm_u + 1023u) & ~1023u;
    const uint32_t uB0 = uA  + 65536u;
    const uint32_t uB1 = uB0 + 65536u;

    const int warp_m = (wid & 3) * 32;   // 4 warps along M
    const int warp_n = (wid >> 2) * 64;  // 2 warps along N

    // ldmatrix lane geometry
    const int rA0   = warp_m + (lane & 15);
    const uint32_t swA = (uint32_t)((rA0 & 7) << 4);
    const uint32_t aKl = (uint32_t)((lane >> 4) << 4);
    const int rB0   = warp_n + (lane & 7) + ((lane >> 4) << 3);
    const uint32_t swB = (uint32_t)((rB0 & 7) << 4);
    const uint32_t bKl = (uint32_t)(((lane >> 3) & 1) << 4);

    uint32_t rbaseA[2], rbaseB[4];
    #pragma unroll
    for (int mf = 0; mf < 2; mf++) rbaseA[mf] = uA + (uint32_t)((rA0 + 16 * mf) << 7);
    #pragma unroll
    for (int np = 0; np < 4; np++) rbaseB[np] = (uint32_t)((rB0 + 16 * np) << 7);

    const float l      = *ls_p;
    const float negInv = -0.5f / (l * l);
    const float sCut   = 211.0f * l * l;   // expf == exactly 0 above this
    const float sv     = *sv_p;
    const bool  force  = (g_sat != 0);

    const int t_begin = (int)(((long long)bid     * TOT_TILES) / GRID);
    const int t_end   = (int)(((long long)(bid+1) * TOT_TILES) / GRID);

    // Linear coalesced fill: gmem is pre-swizzled, so dst == src offsets.
    auto fill_tile = [&](uint32_t ubase, const char* src) {
        #pragma unroll
        for (int q0 = 0; q0 < 16; q0++) {
            const uint32_t o = (uint32_t)(q0 * 256 + tid) * 16u;
            cp16(ubase + o, src + o);
        }
    };

    int i = t_begin;
    while (i < t_end) {
        const int rt      = i >> 6;
        const int seg_end = min(t_end, (rt + 1) << 6);
        const int n       = seg_end - i;
        const int row0    = rt * TM;

        fill_tile(uA, (const char*)g_At + (size_t)rt * TILE_BYTES);
        CP_COMMIT();
        {
            const int ct0 = i & 63;
            fill_tile(uB0, (const char*)g_Bt + (size_t)ct0 * TILE_BYTES);
            CP_COMMIT();
            if (tid < TN) s_yy[0][tid] = g_YY[ct0 * TN + tid];
            else          s_mu[0][tid - TN] = mu[ct0 * TN + tid - TN];
        }

        // per-thread xx values (4 rows of the 32-row warp stripe) + warp min
        float xv[4];
        #pragma unroll
        for (int j = 0; j < 4; j++) xv[j] = g_XX[row0 + warp_m + (lane >> 2) + 8 * j];
        float xmin = fminf(fminf(xv[0], xv[1]), fminf(xv[2], xv[3]));
        #pragma unroll
        for (int o = 16; o > 0; o >>= 1) xmin = fminf(xmin, __shfl_xor_sync(0xffffffffu, xmin, o));

        for (int tl = 0; tl < n; tl++) {
            const int buf = tl & 1;
            const uint32_t uB = buf ? uB1 : uB0;

            const bool more = (tl + 1 < n);
            if (more) {
                const int ctn = (i + tl + 1) & 63;
                fill_tile(buf ? uB0 : uB1, (const char*)g_Bt + (size_t)ctn * TILE_BYTES);
                CP_COMMIT();
                if (tid < TN) s_yy[buf ^ 1][tid] = g_YY[ctn * TN + tid];
                else          s_mu[buf ^ 1][tid - TN] = mu[ctn * TN + tid - TN];
            }
            if (more) asm volatile("cp.async.wait_group 1;" ::: "memory");
            else      asm volatile("cp.async.wait_group 0;" ::: "memory");
            __syncthreads();

            // ---- MMA: 128x128x256, f16 acc, fragment pipeline depth 3 ----
            uint32_t acc[2][8][2];
            #pragma unroll
            for (int mf = 0; mf < 2; mf++)
                #pragma unroll
                for (int nf = 0; nf < 8; nf++) { acc[mf][nf][0] = 0u; acc[mf][nf][1] = 0u; }

            uint32_t a[3][2][4], b[3][4][4];

            auto ld_frags = [&](int kk, uint32_t (&af)[2][4], uint32_t (&bf)[4][4]) {
                const uint32_t kcOff = (uint32_t)((kk >> 2) << 14);
                const uint32_t oA = kcOff + ((((uint32_t)(kk & 3) << 5) + aKl) ^ swA);
                const uint32_t oB = kcOff + ((((uint32_t)(kk & 3) << 5) + bKl) ^ swB);
                #pragma unroll
                for (int mf = 0; mf < 2; mf++) ldsm_x4(af[mf], rbaseA[mf] + oA);
                #pragma unroll
                for (int np = 0; np < 4; np++) ldsm_x4(bf[np], uB + rbaseB[np] + oB);
            };

            ld_frags(0, a[0], b[0]);
            ld_frags(1, a[1], b[1]);
            #pragma unroll
            for (int kk = 0; kk < 16; kk++) {
                const int cur = kk % 3;
                if (kk < 14) {
                    const int nxt = (kk + 2) % 3;
                    ld_frags(kk + 2, a[nxt], b[nxt]);
                }
                #pragma unroll
                for (int mf = 0; mf < 2; mf++)
                    #pragma unroll
                    for (int nf = 0; nf < 8; nf++)
                        mma_f16acc(acc[mf][nf], a[cur][mf],
                                   b[cur][nf >> 1][(nf & 1) * 2], b[cur][nf >> 1][(nf & 1) * 2 + 1]);
            }

            // ---- epilogue: warp-level rigorous screen ----
            __half2 m2 = *(const __half2*)&acc[0][0][0];
            #pragma unroll
            for (int mf = 0; mf < 2; mf++)
                #pragma unroll
                for (int nf = 0; nf < 8; nf++) {
                    m2 = __hmax2(m2, *(const __half2*)&acc[mf][nf][0]);
                    m2 = __hmax2(m2, *(const __half2*)&acc[mf][nf][1]);
                }
            float cmax = fmaxf(__low2float(m2), __high2float(m2));
            #pragma unroll
            for (int o = 16; o > 0; o >>= 1) cmax = fmaxf(cmax, __shfl_xor_sync(0xffffffffu, cmax, o));

            float ymin = fminf(s_yy[buf][warp_n + lane], s_yy[buf][warp_n + 32 + lane]);
            #pragma unroll
            for (int o = 16; o > 0; o >>= 1) ymin = fminf(ymin, __shfl_xor_sync(0xffffffffu, ymin, o));

            const float qmin  = xmin + ymin;                       // q = xx+yy >= 0
            const float lbmin = fmaf(-0.02f, qmin, fmaf(-2.f, cmax, qmin)) - 0.05f;

            if (force || lbmin < sCut) {   // per-element screen + exact fp32 recompute
                float yv[16];
                #pragma unroll
                for (int k2 = 0; k2 < 16; k2++)
                    yv[k2] = s_yy[buf][warp_n + (k2 >> 1) * 8 + 2 * (lane & 3) + (k2 & 1)];
                const int n0 = ((i + tl) & 63) * TN;
                #pragma unroll 1
                for (int mf = 0; mf < 2; mf++)
                    for (int nf = 0; nf < 8; nf++)
                        for (int jj = 0; jj < 2; jj++) {
                            const float2 cv = __half22float2(*(const __half2*)&acc[mf][nf][jj]);
                            #pragma unroll
                            for (int p = 0; p < 2; p++) {
                                const float c  = p ? cv.y : cv.x;
                                const float q  = xv[mf * 2 + jj] + yv[nf * 2 + p];
                                const float s  = fmaf(-2.f, c, q);
                                const float lb = fmaf(-0.02f, q, s) - 0.05f;
                                if (force || lb < sCut) {
                                    const int rg = row0 + warp_m + mf * 16 + (lane >> 2) + 8 * jj;
                                    const int cg = n0 + warp_n + nf * 8 + 2 * (lane & 3) + p;
                                    const float* xr = Xtest  + (size_t)rg * DIM;
                                    const float* yr = Xtrain + (size_t)cg * DIM;
                                    float cr = 0.f;
                                    #pragma unroll 8
                                    for (int d = 0; d < DIM; d++) cr = fmaf(xr[d], yr[d], cr);
                                    const float se = fmaxf(fmaf(-2.f, cr, g_XX[rg] + g_YY[cg]), 0.f);
                                    const float ev = expf(se * negInv);
                                    if (ev != 0.f)
                                        atomicAdd(&out[rg], sv * ev * s_mu[buf][warp_n + nf * 8 + 2 * (lane & 3) + p]);
                                }
                            }
                        }
            }
            __syncthreads();   // epilogue done before buffers are overwritten
        }
        i = seg_end;
    }
}

// ============================================================================
// kernel_launch: inputs in metadata order:
//   0 Xtest, 1 Xtrain, 2 mu, 3 mean_const, 4 lengthscale, 5 signal_var
// ============================================================================
extern "C" void kernel_launch(void* const* d_in, const int* in_sizes, int n_in,
                              void* d_out, int out_size)
{
    const float* Xtest      = (const float*)d_in[0];
    const float* Xtrain     = (const float*)d_in[1];
    const float* mu         = (const float*)d_in[2];
    const float* mean_const = (const float*)d_in[3];
    const float* lengthsc   = (const float*)d_in[4];
    const float* signal_var = (const float*)d_in[5];
    float* out = (float*)d_out;

    const int DYN = 3 * 65536 + 1024;
    cudaFuncSetAttribute(gp_hmma_kernel, cudaFuncAttributeMaxDynamicSharedMemorySize, DYN);

    gp_precompute_kernel<<<(NTEST + NTRAIN) / 8, 256>>>(Xtest, Xtrain, mean_const, out);
    gp_hmma_kernel<<<GRID, 256, DYN>>>(Xtest, Xtrain, mu, lengthsc, signal_var, out);
}